// round 1
// baseline (speedup 1.0000x reference)
#include <cuda_runtime.h>

// 2-layer LSTM: layer1 D=1 -> H=36, ReLU, layer2 36 -> 1. B=2048, T=2048, fp32.
// Persistent per-block recurrence: 256 blocks x 72 threads, 8 batch/block.
// Thread = (unit j in 0..35, batch-group bg in 0..1, 4 batches each).

#define TT   2048
#define H    36
#define BPB  8     // batch elements per block
#define NT   72    // threads per block (2 batch groups * 36 units)
#define TCH  64    // time chunk for x staging / out flushing

__device__ __forceinline__ float sigf(float x) {
    return __fdividef(1.0f, 1.0f + __expf(-x));
}
__device__ __forceinline__ float tanh_f(float x) {
    // 1 - 2/(exp(2x)+1); exact at 0, saturates correctly at +/-inf
    return 1.0f - 2.0f * __fdividef(1.0f, __expf(2.0f * x) + 1.0f);
}

__global__ void __launch_bounds__(NT) lstm2_kernel(
    const float* __restrict__ x,
    const float* __restrict__ Wih1, const float* __restrict__ Whh1,
    const float* __restrict__ bih1, const float* __restrict__ bhh1,
    const float* __restrict__ Wih2, const float* __restrict__ Whh2,
    const float* __restrict__ bih2, const float* __restrict__ bhh2,
    float* __restrict__ out)
{
    // Wsm[k][j] = {W_hh1[i-gate row j][k], f, g, o} -> one LDS.128 = 4 gate weights
    __shared__ float4 Wsm[H][H];                       // 20736 B
    __shared__ __align__(16) float hsm[2][H][12];      // [buf][unit][batch pad 8->12]
    __shared__ float xsm[BPB][TCH];                    // staged input chunk
    __shared__ float osm[BPB][TCH];                    // output chunk buffer
    __shared__ float w2sm[4 * H];                      // W_ih2 [4][36]
    __shared__ float4 psm[2][2][H];                    // layer2 partials [buf][bg][j]

    const int tid = threadIdx.x;
    const int bg  = (tid >= H) ? 1 : 0;    // batch group 0/1
    const int j   = tid - bg * H;          // hidden unit 0..35
    const int bbase = blockIdx.x * BPB;

    // ---- init shared ----
    for (int idx = tid; idx < H * H; idx += NT) {
        const int k = idx / H, jj = idx - (idx / H) * H;
        Wsm[k][jj] = make_float4(Whh1[jj * H + k],
                                 Whh1[(H + jj) * H + k],
                                 Whh1[(2 * H + jj) * H + k],
                                 Whh1[(3 * H + jj) * H + k]);
    }
    for (int idx = tid; idx < 4 * H; idx += NT) w2sm[idx] = Wih2[idx];
    for (int idx = tid; idx < 2 * H * 12; idx += NT) (&hsm[0][0][0])[idx] = 0.0f;
    __syncthreads();

    // per-thread layer1 constants (D=1: x term is scalar * weight)
    const float wx0 = Wih1[j];
    const float wx1 = Wih1[H + j];
    const float wx2 = Wih1[2 * H + j];
    const float wx3 = Wih1[3 * H + j];
    const float bbi = bih1[j]         + bhh1[j];
    const float bbf = bih1[H + j]     + bhh1[H + j];
    const float bbg = bih1[2 * H + j] + bhh1[2 * H + j];
    const float bbo = bih1[3 * H + j] + bhh1[3 * H + j];

    // layer2 partial assignment: thread j handles gate (j&3), k-range [(j>>2)*4, +4)
    const int g2 = j & 3;
    const int k0 = (j >> 2) * 4;
    const float w2a = w2sm[g2 * H + k0 + 0];
    const float w2b = w2sm[g2 * H + k0 + 1];
    const float w2c = w2sm[g2 * H + k0 + 2];
    const float w2d = w2sm[g2 * H + k0 + 3];

    // layer2 scalar-cell state (used by j==0 thread of each bg; 4 batches each)
    float wh2[4], b2c[4], h2v[4], c2v[4];
    #pragma unroll
    for (int g = 0; g < 4; ++g) { h2v[g] = 0.f; c2v[g] = 0.f; wh2[g] = 0.f; b2c[g] = 0.f; }
    if (j == 0) {
        #pragma unroll
        for (int g = 0; g < 4; ++g) { wh2[g] = Whh2[g]; b2c[g] = bih2[g] + bhh2[g]; }
    }

    float c1[4] = {0.f, 0.f, 0.f, 0.f};
    int cur = 0;

    for (int t = 0; t < TT; ++t) {
        const int ti = t & (TCH - 1);
        if (ti == 0) {
            __syncthreads();
            for (int idx = tid; idx < BPB * TCH; idx += NT) {
                const int b = idx >> 6, i2 = idx & (TCH - 1);
                xsm[b][i2] = x[(bbase + b) * TT + t + i2];
            }
            __syncthreads();
        } else if (ti == 1 && t > TCH) {
            __syncthreads();
            const int tb = t - (TCH + 1);
            for (int idx = tid; idx < BPB * TCH; idx += NT) {
                const int b = idx >> 6, i2 = idx & (TCH - 1);
                out[(bbase + b) * TT + tb + i2] = osm[b][i2];
            }
            __syncthreads();
        }

        // ---- main recurrent matvec: 4 gates x 4 batches, reads h1(t-1) ----
        float acc[4][4];
        #pragma unroll
        for (int g = 0; g < 4; ++g) {
            #pragma unroll
            for (int b = 0; b < 4; ++b) acc[g][b] = 0.f;
        }
        #pragma unroll
        for (int k = 0; k < H; ++k) {
            const float4 w  = Wsm[k][j];
            const float4 hv = *(const float4*)&hsm[cur][k][bg * 4];
            acc[0][0] = fmaf(w.x, hv.x, acc[0][0]);
            acc[0][1] = fmaf(w.x, hv.y, acc[0][1]);
            acc[0][2] = fmaf(w.x, hv.z, acc[0][2]);
            acc[0][3] = fmaf(w.x, hv.w, acc[0][3]);
            acc[1][0] = fmaf(w.y, hv.x, acc[1][0]);
            acc[1][1] = fmaf(w.y, hv.y, acc[1][1]);
            acc[1][2] = fmaf(w.y, hv.z, acc[1][2]);
            acc[1][3] = fmaf(w.y, hv.w, acc[1][3]);
            acc[2][0] = fmaf(w.z, hv.x, acc[2][0]);
            acc[2][1] = fmaf(w.z, hv.y, acc[2][1]);
            acc[2][2] = fmaf(w.z, hv.z, acc[2][2]);
            acc[2][3] = fmaf(w.z, hv.w, acc[2][3]);
            acc[3][0] = fmaf(w.w, hv.x, acc[3][0]);
            acc[3][1] = fmaf(w.w, hv.y, acc[3][1]);
            acc[3][2] = fmaf(w.w, hv.z, acc[3][2]);
            acc[3][3] = fmaf(w.w, hv.w, acc[3][3]);
        }

        // ---- layer2 partials for step t-1 (hsm[cur] still holds h1(t-1)) ----
        {
            float4 p = make_float4(0.f, 0.f, 0.f, 0.f);
            const float wreg[4] = {w2a, w2b, w2c, w2d};
            #pragma unroll
            for (int kk = 0; kk < 4; ++kk) {
                const float4 hv = *(const float4*)&hsm[cur][k0 + kk][bg * 4];
                const float w = wreg[kk];
                p.x = fmaf(w, fmaxf(hv.x, 0.f), p.x);
                p.y = fmaf(w, fmaxf(hv.y, 0.f), p.y);
                p.z = fmaf(w, fmaxf(hv.z, 0.f), p.z);
                p.w = fmaf(w, fmaxf(hv.w, 0.f), p.w);
            }
            psm[t & 1][bg][j] = p;
        }

        // ---- activations, write h1(t) ----
        {
            float hh[4];
            #pragma unroll
            for (int b = 0; b < 4; ++b) {
                const float xb = xsm[bg * 4 + b][ti];
                const float gi = fmaf(wx0, xb, acc[0][b] + bbi);
                const float gf = fmaf(wx1, xb, acc[1][b] + bbf);
                const float gg = fmaf(wx2, xb, acc[2][b] + bbg);
                const float go = fmaf(wx3, xb, acc[3][b] + bbo);
                const float c  = sigf(gf) * c1[b] + sigf(gi) * tanh_f(gg);
                c1[b] = c;
                hh[b] = sigf(go) * tanh_f(c);
            }
            *(float4*)&hsm[cur ^ 1][j][bg * 4] = make_float4(hh[0], hh[1], hh[2], hh[3]);
        }

        __syncthreads();  // single barrier per step: h1(t) + partials(t-1) visible

        // ---- layer2 cell update for step t-1 (overlaps peers' next main loop) ----
        if (j == 0 && t > 0) {
            const int pb = t & 1;
            float s[4][4];
            #pragma unroll
            for (int g = 0; g < 4; ++g) {
                float4 a = psm[pb][bg][g];
                #pragma unroll
                for (int seg = 1; seg < 9; ++seg) {
                    const float4 q = psm[pb][bg][seg * 4 + g];
                    a.x += q.x; a.y += q.y; a.z += q.z; a.w += q.w;
                }
                s[g][0] = a.x; s[g][1] = a.y; s[g][2] = a.z; s[g][3] = a.w;
            }
            const int slot = (t - 1) & (TCH - 1);
            #pragma unroll
            for (int b = 0; b < 4; ++b) {
                const float gi = s[0][b] + fmaf(wh2[0], h2v[b], b2c[0]);
                const float gf = s[1][b] + fmaf(wh2[1], h2v[b], b2c[1]);
                const float gg = s[2][b] + fmaf(wh2[2], h2v[b], b2c[2]);
                const float go = s[3][b] + fmaf(wh2[3], h2v[b], b2c[3]);
                const float c  = sigf(gf) * c2v[b] + sigf(gi) * tanh_f(gg);
                c2v[b] = c;
                const float hh = sigf(go) * tanh_f(c);
                h2v[b] = hh;
                osm[bg * 4 + b][slot] = hh;
            }
        }
        cur ^= 1;
    }

    // ---- epilogue: layer2 for step TT-1 (hsm[cur] holds h1(TT-1)) ----
    {
        float4 p = make_float4(0.f, 0.f, 0.f, 0.f);
        const float wreg[4] = {w2a, w2b, w2c, w2d};
        #pragma unroll
        for (int kk = 0; kk < 4; ++kk) {
            const float4 hv = *(const float4*)&hsm[cur][k0 + kk][bg * 4];
            const float w = wreg[kk];
            p.x = fmaf(w, fmaxf(hv.x, 0.f), p.x);
            p.y = fmaf(w, fmaxf(hv.y, 0.f), p.y);
            p.z = fmaf(w, fmaxf(hv.z, 0.f), p.z);
            p.w = fmaf(w, fmaxf(hv.w, 0.f), p.w);
        }
        psm[TT & 1][bg][j] = p;
    }
    __syncthreads();
    if (j == 0) {
        const int pb = TT & 1;
        float s[4][4];
        #pragma unroll
        for (int g = 0; g < 4; ++g) {
            float4 a = psm[pb][bg][g];
            #pragma unroll
            for (int seg = 1; seg < 9; ++seg) {
                const float4 q = psm[pb][bg][seg * 4 + g];
                a.x += q.x; a.y += q.y; a.z += q.z; a.w += q.w;
            }
            s[g][0] = a.x; s[g][1] = a.y; s[g][2] = a.z; s[g][3] = a.w;
        }
        const int slot = (TT - 1) & (TCH - 1);
        #pragma unroll
        for (int b = 0; b < 4; ++b) {
            const float gi = s[0][b] + fmaf(wh2[0], h2v[b], b2c[0]);
            const float gf = s[1][b] + fmaf(wh2[1], h2v[b], b2c[1]);
            const float gg = s[2][b] + fmaf(wh2[2], h2v[b], b2c[2]);
            const float go = s[3][b] + fmaf(wh2[3], h2v[b], b2c[3]);
            const float c  = sigf(gf) * c2v[b] + sigf(gi) * tanh_f(gg);
            c2v[b] = c;
            osm[bg * 4 + b][slot] = sigf(go) * tanh_f(c);
        }
    }
    __syncthreads();
    // flush final chunk [TT-TCH, TT)
    for (int idx = tid; idx < BPB * TCH; idx += NT) {
        const int b = idx >> 6, i2 = idx & (TCH - 1);
        out[(bbase + b) * TT + (TT - TCH) + i2] = osm[b][i2];
    }
}

extern "C" void kernel_launch(void* const* d_in, const int* in_sizes, int n_in,
                              void* d_out, int out_size) {
    (void)in_sizes; (void)n_in; (void)out_size;
    const float* x    = (const float*)d_in[0];
    const float* Wih1 = (const float*)d_in[1];
    const float* Whh1 = (const float*)d_in[2];
    const float* bih1 = (const float*)d_in[3];
    const float* bhh1 = (const float*)d_in[4];
    const float* Wih2 = (const float*)d_in[5];
    const float* Whh2 = (const float*)d_in[6];
    const float* bih2 = (const float*)d_in[7];
    const float* bhh2 = (const float*)d_in[8];
    float* out = (float*)d_out;

    const int blocks = 2048 / BPB;  // 256
    lstm2_kernel<<<blocks, NT>>>(x, Wih1, Whh1, bih1, bhh1,
                                 Wih2, Whh2, bih2, bhh2, out);
}

// round 2
// speedup vs baseline: 1.7765x; 1.7765x over previous
#include <cuda_runtime.h>

// 2-layer LSTM: layer1 D=1 -> H=36, ReLU, layer2 36 -> 1. B=2048, T=2048, fp32.
// 256 blocks x 192 threads:
//   tids 0..143  : layer1. thread=(bg=tid/72, r=tid%72, j=r>>1, kh=r&1).
//                  Each owns 18 k-steps (kh half) x 4 gates in registers,
//                  4 batches via packed f32x2 FMA, pair-reduce via shfl.xor 1.
//   tids 144..159: idle (barrier participants only).
//   tids 160..191: dedicated layer-2 warp (2 bgs x 16 lanes: gate g2=sub&3,
//                  k-segment sg=sub>>2), overlaps layer-1 compute each step.

#define TT   2048
#define H    36
#define BPB  8
#define NT   192
#define TCH  64

typedef unsigned long long u64;

__device__ __forceinline__ u64 pk2(float lo, float hi) {
    u64 r; asm("mov.b64 %0,{%1,%2};" : "=l"(r) : "f"(lo), "f"(hi)); return r;
}
__device__ __forceinline__ void upk2(u64 v, float& lo, float& hi) {
    asm("mov.b64 {%0,%1},%2;" : "=f"(lo), "=f"(hi) : "l"(v));
}
__device__ __forceinline__ u64 fma2(u64 a, u64 b, u64 c) {
    u64 d; asm("fma.rn.f32x2 %0,%1,%2,%3;" : "=l"(d) : "l"(a), "l"(b), "l"(c)); return d;
}
__device__ __forceinline__ u64 add2(u64 a, u64 b) {
    u64 d; asm("add.rn.f32x2 %0,%1,%2;" : "=l"(d) : "l"(a), "l"(b)); return d;
}

__device__ __forceinline__ float sigf(float x)   { return __fdividef(1.0f, 1.0f + __expf(-x)); }
__device__ __forceinline__ float tanh_f(float x) { return 1.0f - 2.0f * __fdividef(1.0f, __expf(2.0f * x) + 1.0f); }

__global__ void __launch_bounds__(NT, 2) lstm2_kernel(
    const float* __restrict__ x,
    const float* __restrict__ Wih1, const float* __restrict__ Whh1,
    const float* __restrict__ bih1, const float* __restrict__ bhh1,
    const float* __restrict__ Wih2, const float* __restrict__ Whh2,
    const float* __restrict__ bih2, const float* __restrict__ bhh2,
    float* __restrict__ out)
{
    __shared__ __align__(16) float hsm[2][H][12];   // [buf][unit][8 batches pad 12]
    __shared__ float xsm[BPB][TCH];
    __shared__ float osm[BPB][TCH];

    const int tid   = threadIdx.x;
    const int bbase = blockIdx.x * BPB;
    const bool isL1 = (tid < 144);
    const bool isL2 = (tid >= 160);
    // warp 4 (tids 128..159) has only lanes 0..15 doing layer-1 shuffles
    const unsigned lmask = ((tid >> 5) == 4) ? 0x0000FFFFu : 0xFFFFFFFFu;

    // ---- zero h state ----
    for (int i = tid; i < 2 * H * 12; i += NT) (&hsm[0][0][0])[i] = 0.0f;

    // ---- layer-1 thread identity + register weights ----
    int bg = 0, j = 0, kh = 0;
    u64 w1p[18][2];                 // packed {w_i,w_f} and {w_g,w_o} per k
    float wx0=0, wx1=0, wx2=0, wx3=0, bbi=0, bbf=0, bbg=0, bbo=0;
    float c1a = 0.0f, c1b = 0.0f;
    if (isL1) {
        bg = tid / 72; const int r = tid % 72; j = r >> 1; kh = r & 1;
        const int kb = kh * 18;
        #pragma unroll
        for (int kk = 0; kk < 18; ++kk) {
            const int k = kb + kk;
            w1p[kk][0] = pk2(Whh1[j * H + k],           Whh1[(H + j) * H + k]);
            w1p[kk][1] = pk2(Whh1[(2 * H + j) * H + k], Whh1[(3 * H + j) * H + k]);
        }
        wx0 = Wih1[j]; wx1 = Wih1[H + j]; wx2 = Wih1[2 * H + j]; wx3 = Wih1[3 * H + j];
        bbi = bih1[j]         + bhh1[j];
        bbf = bih1[H + j]     + bhh1[H + j];
        bbg = bih1[2 * H + j] + bhh1[2 * H + j];
        bbo = bih1[3 * H + j] + bhh1[3 * H + j];
    }

    // ---- layer-2 warp identity ----
    int bgl = 0, g2 = 0, sg = 0, sub = 0;
    float w2r[9]; float b2 = 0.0f, wh2g = 0.0f;
    float sA = 1.0f, sQ = 1.0f, sR = 0.0f;   // act(v) = sR + sQ * tanh(sA * v)
    float c2[4] = {0, 0, 0, 0}, h2[4] = {0, 0, 0, 0};
    if (isL2) {
        const int l = tid - 160; bgl = l >> 4; sub = l & 15; g2 = sub & 3; sg = sub >> 2;
        #pragma unroll
        for (int s = 0; s < 9; ++s) w2r[s] = Wih2[g2 * H + sg * 9 + s];
        b2 = bih2[g2] + bhh2[g2];
        wh2g = Whh2[g2];
        if (g2 != 2) { sA = 0.5f; sQ = 0.5f; sR = 0.5f; }   // sigmoid via tanh
    }
    __syncthreads();

    int cur = 0;
    for (int t = 0; t <= TT; ++t) {
        const int ti = t & (TCH - 1);
        if (ti == 0 && t < TT) {
            __syncthreads();
            for (int idx = tid; idx < BPB * TCH; idx += NT) {
                const int b = idx >> 6, i2 = idx & (TCH - 1);
                xsm[b][i2] = x[(bbase + b) * TT + t + i2];
            }
            __syncthreads();
        } else if (ti == 1 && t > TCH) {
            __syncthreads();
            const int tb = t - (TCH + 1);
            for (int idx = tid; idx < BPB * TCH; idx += NT) {
                const int b = idx >> 6, i2 = idx & (TCH - 1);
                out[(bbase + b) * TT + tb + i2] = osm[b][i2];
            }
            __syncthreads();
        }

        if (isL1 && t < TT) {
            // ---- recurrent matvec: packed gate-pairs, 4 batches, 18 k-steps ----
            u64 a0[4] = {0, 0, 0, 0};   // {gate_i, gate_f} per batch
            u64 a1[4] = {0, 0, 0, 0};   // {gate_g, gate_o} per batch
            const int kb = kh * 18;
            #pragma unroll
            for (int kk = 0; kk < 18; ++kk) {
                const float4 hv = *(const float4*)&hsm[cur][kb + kk][bg * 4];
                const u64 hb0 = pk2(hv.x, hv.x);
                const u64 hb1 = pk2(hv.y, hv.y);
                const u64 hb2 = pk2(hv.z, hv.z);
                const u64 hb3 = pk2(hv.w, hv.w);
                const u64 wA = w1p[kk][0], wB = w1p[kk][1];
                a0[0] = fma2(wA, hb0, a0[0]); a1[0] = fma2(wB, hb0, a1[0]);
                a0[1] = fma2(wA, hb1, a0[1]); a1[1] = fma2(wB, hb1, a1[1]);
                a0[2] = fma2(wA, hb2, a0[2]); a1[2] = fma2(wB, hb2, a1[2]);
                a0[3] = fma2(wA, hb3, a0[3]); a1[3] = fma2(wB, hb3, a1[3]);
            }
            // ---- pair reduction over k-halves (partner = adjacent lane) ----
            #pragma unroll
            for (int b = 0; b < 4; ++b) {
                a0[b] = add2(a0[b], __shfl_xor_sync(lmask, a0[b], 1));
                a1[b] = add2(a1[b], __shfl_xor_sync(lmask, a1[b], 1));
            }
            // ---- activations for my 2 batches (li = kh*2) ----
            const int li = kh * 2;
            float gi0, gf0, gg0, go0, gi1, gf1, gg1, go1;
            upk2(a0[li],     gi0, gf0);
            upk2(a1[li],     gg0, go0);
            upk2(a0[li + 1], gi1, gf1);
            upk2(a1[li + 1], gg1, go1);
            const float xb0 = xsm[bg * 4 + li][ti];
            const float xb1 = xsm[bg * 4 + li + 1][ti];
            gi0 = fmaf(wx0, xb0, gi0 + bbi); gi1 = fmaf(wx0, xb1, gi1 + bbi);
            gf0 = fmaf(wx1, xb0, gf0 + bbf); gf1 = fmaf(wx1, xb1, gf1 + bbf);
            gg0 = fmaf(wx2, xb0, gg0 + bbg); gg1 = fmaf(wx2, xb1, gg1 + bbg);
            go0 = fmaf(wx3, xb0, go0 + bbo); go1 = fmaf(wx3, xb1, go1 + bbo);
            const float cc0 = sigf(gf0) * c1a + sigf(gi0) * tanh_f(gg0);
            const float cc1 = sigf(gf1) * c1b + sigf(gi1) * tanh_f(gg1);
            c1a = cc0; c1b = cc1;
            const float hh0 = sigf(go0) * tanh_f(cc0);
            const float hh1 = sigf(go1) * tanh_f(cc1);
            *(float2*)&hsm[cur ^ 1][j][bg * 4 + li] = make_float2(hh0, hh1);
        } else if (isL2 && t >= 1) {
            // ---- layer 2 for time t-1: reads h1(t-1) = hsm[cur] ----
            float4 p = make_float4(0.f, 0.f, 0.f, 0.f);
            #pragma unroll
            for (int s = 0; s < 9; ++s) {
                const float4 hv = *(const float4*)&hsm[cur][sg * 9 + s][bgl * 4];
                const float w = w2r[s];
                p.x = fmaf(w, fmaxf(hv.x, 0.f), p.x);
                p.y = fmaf(w, fmaxf(hv.y, 0.f), p.y);
                p.z = fmaf(w, fmaxf(hv.z, 0.f), p.z);
                p.w = fmaf(w, fmaxf(hv.w, 0.f), p.w);
            }
            // reduce over 4 k-segments (lanes xor 4, xor 8 within 16-group)
            #pragma unroll
            for (int off = 4; off <= 8; off <<= 1) {
                p.x += __shfl_xor_sync(0xFFFFFFFFu, p.x, off);
                p.y += __shfl_xor_sync(0xFFFFFFFFu, p.y, off);
                p.z += __shfl_xor_sync(0xFFFFFFFFu, p.z, off);
                p.w += __shfl_xor_sync(0xFFFFFFFFu, p.w, off);
            }
            // add recurrent + bias, then activation (branchless sig/tanh)
            float4 a;
            {
                const float v0 = p.x + fmaf(wh2g, h2[0], b2);
                const float v1 = p.y + fmaf(wh2g, h2[1], b2);
                const float v2 = p.z + fmaf(wh2g, h2[2], b2);
                const float v3 = p.w + fmaf(wh2g, h2[3], b2);
                a.x = fmaf(sQ, tanh_f(sA * v0), sR);
                a.y = fmaf(sQ, tanh_f(sA * v1), sR);
                a.z = fmaf(sQ, tanh_f(sA * v2), sR);
                a.w = fmaf(sQ, tanh_f(sA * v3), sR);
            }
            // gather all 4 activated gates from lanes bgl*16 + g
            const int lb = bgl * 16;
            float4 Gi, Gf, Gg, Go;
            Gi.x = __shfl_sync(0xFFFFFFFFu, a.x, lb + 0);
            Gi.y = __shfl_sync(0xFFFFFFFFu, a.y, lb + 0);
            Gi.z = __shfl_sync(0xFFFFFFFFu, a.z, lb + 0);
            Gi.w = __shfl_sync(0xFFFFFFFFu, a.w, lb + 0);
            Gf.x = __shfl_sync(0xFFFFFFFFu, a.x, lb + 1);
            Gf.y = __shfl_sync(0xFFFFFFFFu, a.y, lb + 1);
            Gf.z = __shfl_sync(0xFFFFFFFFu, a.z, lb + 1);
            Gf.w = __shfl_sync(0xFFFFFFFFu, a.w, lb + 1);
            Gg.x = __shfl_sync(0xFFFFFFFFu, a.x, lb + 2);
            Gg.y = __shfl_sync(0xFFFFFFFFu, a.y, lb + 2);
            Gg.z = __shfl_sync(0xFFFFFFFFu, a.z, lb + 2);
            Gg.w = __shfl_sync(0xFFFFFFFFu, a.w, lb + 2);
            Go.x = __shfl_sync(0xFFFFFFFFu, a.x, lb + 3);
            Go.y = __shfl_sync(0xFFFFFFFFu, a.y, lb + 3);
            Go.z = __shfl_sync(0xFFFFFFFFu, a.z, lb + 3);
            Go.w = __shfl_sync(0xFFFFFFFFu, a.w, lb + 3);
            // combine (redundant across the 16-group: keeps h2/c2 local)
            c2[0] = Gf.x * c2[0] + Gi.x * Gg.x;
            c2[1] = Gf.y * c2[1] + Gi.y * Gg.y;
            c2[2] = Gf.z * c2[2] + Gi.z * Gg.z;
            c2[3] = Gf.w * c2[3] + Gi.w * Gg.w;
            h2[0] = Go.x * tanh_f(c2[0]);
            h2[1] = Go.y * tanh_f(c2[1]);
            h2[2] = Go.z * tanh_f(c2[2]);
            h2[3] = Go.w * tanh_f(c2[3]);
            if (sub == 0) {
                const int slot = (t - 1) & (TCH - 1);
                osm[bgl * 4 + 0][slot] = h2[0];
                osm[bgl * 4 + 1][slot] = h2[1];
                osm[bgl * 4 + 2][slot] = h2[2];
                osm[bgl * 4 + 3][slot] = h2[3];
            }
        }

        __syncthreads();
        cur ^= 1;
    }

    // ---- flush final chunk [TT-TCH, TT) ----
    for (int idx = tid; idx < BPB * TCH; idx += NT) {
        const int b = idx >> 6, i2 = idx & (TCH - 1);
        out[(bbase + b) * TT + (TT - TCH) + i2] = osm[b][i2];
    }
}

extern "C" void kernel_launch(void* const* d_in, const int* in_sizes, int n_in,
                              void* d_out, int out_size) {
    (void)in_sizes; (void)n_in; (void)out_size;
    const float* x    = (const float*)d_in[0];
    const float* Wih1 = (const float*)d_in[1];
    const float* Whh1 = (const float*)d_in[2];
    const float* bih1 = (const float*)d_in[3];
    const float* bhh1 = (const float*)d_in[4];
    const float* Wih2 = (const float*)d_in[5];
    const float* Whh2 = (const float*)d_in[6];
    const float* bih2 = (const float*)d_in[7];
    const float* bhh2 = (const float*)d_in[8];
    float* out = (float*)d_out;

    lstm2_kernel<<<2048 / BPB, NT>>>(x, Wih1, Whh1, bih1, bhh1,
                                     Wih2, Whh2, bih2, bhh2, out);
}

// round 3
// speedup vs baseline: 1.8149x; 1.0216x over previous
#include <cuda_runtime.h>

// 2-layer LSTM: layer1 D=1 -> H=36, ReLU, layer2 36 -> 1. B=2048, T=2048, fp32.
// 256 blocks x 192 threads:
//   tids 0..143  : layer1. thread=(bg=tid/72, r=tid%72, j=r>>1, kh=r&1).
//                  18 k-steps x 4 gates in registers (packed f32x2 gate pairs),
//                  4 batches; h stored DUPLICATED in shared so ulonglong2 loads
//                  give ready-packed {h,h} operands (no movs). Pair-reduce shfl.
//   tids 160..191: dedicated layer-2 warp, overlaps layer-1 compute each step.
// Activations via tanh.approx.f32 (sigmoid = 0.5*tanh(0.5x)+0.5).

#define TT   2048
#define H    36
#define BPB  8
#define NT   192
#define TCH  64

typedef unsigned long long u64;

__device__ __forceinline__ u64 pk2(float lo, float hi) {
    u64 r; asm("mov.b64 %0,{%1,%2};" : "=l"(r) : "f"(lo), "f"(hi)); return r;
}
__device__ __forceinline__ void upk2(u64 v, float& lo, float& hi) {
    asm("mov.b64 {%0,%1},%2;" : "=f"(lo), "=f"(hi) : "l"(v));
}
__device__ __forceinline__ u64 fma2(u64 a, u64 b, u64 c) {
    u64 d; asm("fma.rn.f32x2 %0,%1,%2,%3;" : "=l"(d) : "l"(a), "l"(b), "l"(c)); return d;
}
__device__ __forceinline__ u64 add2(u64 a, u64 b) {
    u64 d; asm("add.rn.f32x2 %0,%1,%2;" : "=l"(d) : "l"(a), "l"(b)); return d;
}
__device__ __forceinline__ float tanhap(float x) {
    float y; asm("tanh.approx.f32 %0,%1;" : "=f"(y) : "f"(x)); return y;
}
__device__ __forceinline__ float sigap(float x) {
    return fmaf(0.5f, tanhap(0.5f * x), 0.5f);
}

__global__ void __launch_bounds__(NT, 2) lstm2_kernel(
    const float* __restrict__ x,
    const float* __restrict__ Wih1, const float* __restrict__ Whh1,
    const float* __restrict__ bih1, const float* __restrict__ bhh1,
    const float* __restrict__ Wih2, const float* __restrict__ Whh2,
    const float* __restrict__ bih2, const float* __restrict__ bhh2,
    float* __restrict__ out)
{
    // h duplicated: hsm[buf][unit][16] = {b0,b0,b1,b1,b2,b2,b3,b3, b4,b4,...,b7,b7}
    __shared__ __align__(16) float hsm[2][H][16];
    __shared__ float xsm[BPB][TCH];
    __shared__ float osm[BPB][TCH];

    const int tid   = threadIdx.x;
    const int bbase = blockIdx.x * BPB;
    const bool isL1 = (tid < 144);
    const bool isL2 = (tid >= 160);
    // warp 4 (tids 128..159): only lanes 0..15 participate in L1 shuffles
    const unsigned lmask = ((tid >> 5) == 4) ? 0x0000FFFFu : 0xFFFFFFFFu;

    for (int i = tid; i < 2 * H * 16; i += NT) (&hsm[0][0][0])[i] = 0.0f;

    // ---- layer-1 identity + register weights ----
    int bg = 0, j = 0, kh = 0;
    u64 w1p[18][2];                 // packed {w_i,w_f} and {w_g,w_o} per k
    float wx0=0, wx1=0, wx2=0, wx3=0, bbi=0, bbf=0, bbg=0, bbo=0;
    float c1a = 0.0f, c1b = 0.0f;
    if (isL1) {
        bg = tid / 72; const int r = tid % 72; j = r >> 1; kh = r & 1;
        const int kb = kh * 18;
        #pragma unroll
        for (int kk = 0; kk < 18; ++kk) {
            const int k = kb + kk;
            w1p[kk][0] = pk2(Whh1[j * H + k],           Whh1[(H + j) * H + k]);
            w1p[kk][1] = pk2(Whh1[(2 * H + j) * H + k], Whh1[(3 * H + j) * H + k]);
        }
        wx0 = Wih1[j]; wx1 = Wih1[H + j]; wx2 = Wih1[2 * H + j]; wx3 = Wih1[3 * H + j];
        bbi = bih1[j]         + bhh1[j];
        bbf = bih1[H + j]     + bhh1[H + j];
        bbg = bih1[2 * H + j] + bhh1[2 * H + j];
        bbo = bih1[3 * H + j] + bhh1[3 * H + j];
    }

    // ---- layer-2 warp identity ----
    int bgl = 0, g2 = 0, sg = 0, sub = 0;
    float w2r[9]; float b2 = 0.0f, wh2g = 0.0f;
    float sA = 1.0f, sQ = 1.0f, sR = 0.0f;   // act(v) = sR + sQ*tanh(sA*v)
    float c2[4] = {0, 0, 0, 0}, h2[4] = {0, 0, 0, 0};
    if (isL2) {
        const int l = tid - 160; bgl = l >> 4; sub = l & 15; g2 = sub & 3; sg = sub >> 2;
        #pragma unroll
        for (int s = 0; s < 9; ++s) w2r[s] = Wih2[g2 * H + sg * 9 + s];
        b2 = bih2[g2] + bhh2[g2];
        wh2g = Whh2[g2];
        if (g2 != 2) { sA = 0.5f; sQ = 0.5f; sR = 0.5f; }   // sigmoid via tanh
    }
    __syncthreads();

    int cur = 0;
    for (int t = 0; t <= TT; ++t) {
        const int ti = t & (TCH - 1);
        if (ti == 0 && t < TT) {
            __syncthreads();
            for (int idx = tid; idx < BPB * TCH; idx += NT) {
                const int b = idx >> 6, i2 = idx & (TCH - 1);
                xsm[b][i2] = x[(bbase + b) * TT + t + i2];
            }
            __syncthreads();
        } else if (ti == 1 && t > TCH) {
            __syncthreads();
            const int tb = t - (TCH + 1);
            for (int idx = tid; idx < BPB * TCH; idx += NT) {
                const int b = idx >> 6, i2 = idx & (TCH - 1);
                out[(bbase + b) * TT + tb + i2] = osm[b][i2];
            }
            __syncthreads();
        }

        if (isL1 && t < TT) {
            // ---- matvec: packed gate-pairs, 4 batches, 18 k; zero-mov operands ----
            u64 a0[4] = {0, 0, 0, 0};   // {i,f} per batch
            u64 a1[4] = {0, 0, 0, 0};   // {g,o} per batch
            const int kb = kh * 18;
            #pragma unroll
            for (int kk = 0; kk < 18; ++kk) {
                const ulonglong2 p01 = *(const ulonglong2*)&hsm[cur][kb + kk][bg * 8];
                const ulonglong2 p23 = *(const ulonglong2*)&hsm[cur][kb + kk][bg * 8 + 4];
                const u64 wA = w1p[kk][0], wB = w1p[kk][1];
                a0[0] = fma2(wA, p01.x, a0[0]); a1[0] = fma2(wB, p01.x, a1[0]);
                a0[1] = fma2(wA, p01.y, a0[1]); a1[1] = fma2(wB, p01.y, a1[1]);
                a0[2] = fma2(wA, p23.x, a0[2]); a1[2] = fma2(wB, p23.x, a1[2]);
                a0[3] = fma2(wA, p23.y, a0[3]); a1[3] = fma2(wB, p23.y, a1[3]);
            }
            // ---- pair reduction over the two k-halves (partner = lane xor 1) ----
            #pragma unroll
            for (int b = 0; b < 4; ++b) {
                a0[b] = add2(a0[b], __shfl_xor_sync(lmask, a0[b], 1));
                a1[b] = add2(a1[b], __shfl_xor_sync(lmask, a1[b], 1));
            }
            // ---- activations for my 2 batches (li = kh*2) ----
            const int li = kh * 2;
            float gi0, gf0, gg0, go0, gi1, gf1, gg1, go1;
            upk2(a0[li],     gi0, gf0);
            upk2(a1[li],     gg0, go0);
            upk2(a0[li + 1], gi1, gf1);
            upk2(a1[li + 1], gg1, go1);
            const float xb0 = xsm[bg * 4 + li][ti];
            const float xb1 = xsm[bg * 4 + li + 1][ti];
            gi0 = fmaf(wx0, xb0, gi0 + bbi); gi1 = fmaf(wx0, xb1, gi1 + bbi);
            gf0 = fmaf(wx1, xb0, gf0 + bbf); gf1 = fmaf(wx1, xb1, gf1 + bbf);
            gg0 = fmaf(wx2, xb0, gg0 + bbg); gg1 = fmaf(wx2, xb1, gg1 + bbg);
            go0 = fmaf(wx3, xb0, go0 + bbo); go1 = fmaf(wx3, xb1, go1 + bbo);
            const float cc0 = sigap(gf0) * c1a + sigap(gi0) * tanhap(gg0);
            const float cc1 = sigap(gf1) * c1b + sigap(gi1) * tanhap(gg1);
            c1a = cc0; c1b = cc1;
            const float hh0 = sigap(go0) * tanhap(cc0);
            const float hh1 = sigap(go1) * tanhap(cc1);
            // duplicated store: {h0,h0,h1,h1} -> one STS.128
            *(float4*)&hsm[cur ^ 1][j][bg * 8 + li * 2] = make_float4(hh0, hh0, hh1, hh1);
        } else if (isL2 && t >= 1) {
            // ---- layer 2 for time t-1: reads h1(t-1) = hsm[cur] (dup layout) ----
            float4 p = make_float4(0.f, 0.f, 0.f, 0.f);
            #pragma unroll
            for (int s = 0; s < 9; ++s) {
                const float4 q01 = *(const float4*)&hsm[cur][sg * 9 + s][bgl * 8];
                const float4 q23 = *(const float4*)&hsm[cur][sg * 9 + s][bgl * 8 + 4];
                const float w = w2r[s];
                p.x = fmaf(w, fmaxf(q01.x, 0.f), p.x);
                p.y = fmaf(w, fmaxf(q01.z, 0.f), p.y);
                p.z = fmaf(w, fmaxf(q23.x, 0.f), p.z);
                p.w = fmaf(w, fmaxf(q23.z, 0.f), p.w);
            }
            #pragma unroll
            for (int off = 4; off <= 8; off <<= 1) {
                p.x += __shfl_xor_sync(0xFFFFFFFFu, p.x, off);
                p.y += __shfl_xor_sync(0xFFFFFFFFu, p.y, off);
                p.z += __shfl_xor_sync(0xFFFFFFFFu, p.z, off);
                p.w += __shfl_xor_sync(0xFFFFFFFFu, p.w, off);
            }
            float4 a;
            {
                const float v0 = p.x + fmaf(wh2g, h2[0], b2);
                const float v1 = p.y + fmaf(wh2g, h2[1], b2);
                const float v2 = p.z + fmaf(wh2g, h2[2], b2);
                const float v3 = p.w + fmaf(wh2g, h2[3], b2);
                a.x = fmaf(sQ, tanhap(sA * v0), sR);
                a.y = fmaf(sQ, tanhap(sA * v1), sR);
                a.z = fmaf(sQ, tanhap(sA * v2), sR);
                a.w = fmaf(sQ, tanhap(sA * v3), sR);
            }
            const int lb = bgl * 16;
            float4 Gi, Gf, Gg, Go;
            Gi.x = __shfl_sync(0xFFFFFFFFu, a.x, lb + 0);
            Gi.y = __shfl_sync(0xFFFFFFFFu, a.y, lb + 0);
            Gi.z = __shfl_sync(0xFFFFFFFFu, a.z, lb + 0);
            Gi.w = __shfl_sync(0xFFFFFFFFu, a.w, lb + 0);
            Gf.x = __shfl_sync(0xFFFFFFFFu, a.x, lb + 1);
            Gf.y = __shfl_sync(0xFFFFFFFFu, a.y, lb + 1);
            Gf.z = __shfl_sync(0xFFFFFFFFu, a.z, lb + 1);
            Gf.w = __shfl_sync(0xFFFFFFFFu, a.w, lb + 1);
            Gg.x = __shfl_sync(0xFFFFFFFFu, a.x, lb + 2);
            Gg.y = __shfl_sync(0xFFFFFFFFu, a.y, lb + 2);
            Gg.z = __shfl_sync(0xFFFFFFFFu, a.z, lb + 2);
            Gg.w = __shfl_sync(0xFFFFFFFFu, a.w, lb + 2);
            Go.x = __shfl_sync(0xFFFFFFFFu, a.x, lb + 3);
            Go.y = __shfl_sync(0xFFFFFFFFu, a.y, lb + 3);
            Go.z = __shfl_sync(0xFFFFFFFFu, a.z, lb + 3);
            Go.w = __shfl_sync(0xFFFFFFFFu, a.w, lb + 3);
            c2[0] = Gf.x * c2[0] + Gi.x * Gg.x;
            c2[1] = Gf.y * c2[1] + Gi.y * Gg.y;
            c2[2] = Gf.z * c2[2] + Gi.z * Gg.z;
            c2[3] = Gf.w * c2[3] + Gi.w * Gg.w;
            h2[0] = Go.x * tanhap(c2[0]);
            h2[1] = Go.y * tanhap(c2[1]);
            h2[2] = Go.z * tanhap(c2[2]);
            h2[3] = Go.w * tanhap(c2[3]);
            if (sub == 0) {
                const int slot = (t - 1) & (TCH - 1);
                osm[bgl * 4 + 0][slot] = h2[0];
                osm[bgl * 4 + 1][slot] = h2[1];
                osm[bgl * 4 + 2][slot] = h2[2];
                osm[bgl * 4 + 3][slot] = h2[3];
            }
        }

        __syncthreads();
        cur ^= 1;
    }

    // ---- flush final chunk [TT-TCH, TT) ----
    for (int idx = tid; idx < BPB * TCH; idx += NT) {
        const int b = idx >> 6, i2 = idx & (TCH - 1);
        out[(bbase + b) * TT + (TT - TCH) + i2] = osm[b][i2];
    }
}

extern "C" void kernel_launch(void* const* d_in, const int* in_sizes, int n_in,
                              void* d_out, int out_size) {
    (void)in_sizes; (void)n_in; (void)out_size;
    const float* x    = (const float*)d_in[0];
    const float* Wih1 = (const float*)d_in[1];
    const float* Whh1 = (const float*)d_in[2];
    const float* bih1 = (const float*)d_in[3];
    const float* bhh1 = (const float*)d_in[4];
    const float* Wih2 = (const float*)d_in[5];
    const float* Whh2 = (const float*)d_in[6];
    const float* bih2 = (const float*)d_in[7];
    const float* bhh2 = (const float*)d_in[8];
    float* out = (float*)d_out;

    lstm2_kernel<<<2048 / BPB, NT>>>(x, Wih1, Whh1, bih1, bhh1,
                                     Wih2, Whh2, bih2, bhh2, out);
}

// round 5
// speedup vs baseline: 1.8564x; 1.0229x over previous
#include <cuda_runtime.h>

// 2-layer LSTM: layer1 D=1 -> H=36, ReLU, layer2 36 -> 1. B=2048, T=2048, fp32.
// 256 blocks x 320 threads:
//   tids 0..287 (warps 0..8, all full): layer1. thread=(bg=tid/144, r=tid%144,
//     j=r>>2, kq=r&3). Each owns 9 k-steps x 4 gates x 4 batches in packed
//     f32x2 registers; quad reduce-scatter (xor2,xor1) leaves each lane with
//     gates for batch bg*4+kq; 5 MUFU activations per thread.
//   tids 288..319 (warp 9): dedicated layer-2 warp (2 bg x 16 lanes).
// h stored duplicated {h,h} per batch, row stride 20 floats (bank-spread).

#define TT   2048
#define H    36
#define HS   20     // hsm row stride in floats
#define BPB  8
#define NT   320
#define TCH  64

typedef unsigned long long u64;

__device__ __forceinline__ u64 pk2(float lo, float hi) {
    u64 r; asm("mov.b64 %0,{%1,%2};" : "=l"(r) : "f"(lo), "f"(hi)); return r;
}
__device__ __forceinline__ void upk2(u64 v, float& lo, float& hi) {
    asm("mov.b64 {%0,%1},%2;" : "=f"(lo), "=f"(hi) : "l"(v));
}
__device__ __forceinline__ u64 fma2(u64 a, u64 b, u64 c) {
    u64 d; asm("fma.rn.f32x2 %0,%1,%2,%3;" : "=l"(d) : "l"(a), "l"(b), "l"(c)); return d;
}
__device__ __forceinline__ u64 add2(u64 a, u64 b) {
    u64 d; asm("add.rn.f32x2 %0,%1,%2;" : "=l"(d) : "l"(a), "l"(b)); return d;
}
__device__ __forceinline__ u64 shfl64(u64 v, int lanexor) {
    return __shfl_xor_sync(0xFFFFFFFFu, v, lanexor);
}
__device__ __forceinline__ float tanhap(float x) {
    float y; asm("tanh.approx.f32 %0,%1;" : "=f"(y) : "f"(x)); return y;
}
__device__ __forceinline__ float sigap(float x) {
    return fmaf(0.5f, tanhap(0.5f * x), 0.5f);
}

__global__ void __launch_bounds__(NT, 2) lstm2_kernel(
    const float* __restrict__ x,
    const float* __restrict__ Wih1, const float* __restrict__ Whh1,
    const float* __restrict__ bih1, const float* __restrict__ bhh1,
    const float* __restrict__ Wih2, const float* __restrict__ Whh2,
    const float* __restrict__ bih2, const float* __restrict__ bhh2,
    float* __restrict__ out)
{
    // duplicated h: hsm[buf][unit][bg*8 + b*2 + {0,1}] = h(batch bg*4+b)
    __shared__ __align__(16) float hsm[2][H][HS];
    __shared__ float xsm[BPB][TCH];
    __shared__ float osm[BPB][TCH];

    const int tid   = threadIdx.x;
    const int bbase = blockIdx.x * BPB;
    const bool isL1 = (tid < 288);
    const bool isL2 = (tid >= 288);

    for (int i = tid; i < 2 * H * HS; i += NT) (&hsm[0][0][0])[i] = 0.0f;

    // ---- layer-1 identity + register weights ----
    int bg = 0, j = 0, kq = 0;
    u64 w1p[9][2];                   // packed {w_i,w_f},{w_g,w_o} per k
    u64 bias0 = 0, bias1 = 0;        // packed biases, only on kq==0 lanes
    float wx0=0, wx1=0, wx2=0, wx3=0;
    float c1 = 0.0f;
    if (isL1) {
        bg = tid / 144; const int r = tid % 144; j = r >> 2; kq = r & 3;
        const int kb = kq * 9;
        #pragma unroll
        for (int kk = 0; kk < 9; ++kk) {
            const int k = kb + kk;
            w1p[kk][0] = pk2(Whh1[j * H + k],           Whh1[(H + j) * H + k]);
            w1p[kk][1] = pk2(Whh1[(2 * H + j) * H + k], Whh1[(3 * H + j) * H + k]);
        }
        wx0 = Wih1[j]; wx1 = Wih1[H + j]; wx2 = Wih1[2 * H + j]; wx3 = Wih1[3 * H + j];
        if (kq == 0) {
            bias0 = pk2(bih1[j] + bhh1[j],                 bih1[H + j] + bhh1[H + j]);
            bias1 = pk2(bih1[2 * H + j] + bhh1[2 * H + j], bih1[3 * H + j] + bhh1[3 * H + j]);
        }
    }

    // ---- layer-2 warp identity ----
    int bgl = 0, g2 = 0, sg = 0, sub = 0;
    float w2r[9]; float b2 = 0.0f, wh2g = 0.0f;
    float sA = 1.0f, sQ = 1.0f, sR = 0.0f;   // act(v) = sR + sQ*tanh(sA*v)
    float c2[4] = {0, 0, 0, 0}, h2[4] = {0, 0, 0, 0};
    if (isL2) {
        const int l = tid - 288; bgl = l >> 4; sub = l & 15; g2 = sub & 3; sg = sub >> 2;
        #pragma unroll
        for (int s = 0; s < 9; ++s) w2r[s] = Wih2[g2 * H + sg * 9 + s];
        b2 = bih2[g2] + bhh2[g2];
        wh2g = Whh2[g2];
        if (g2 != 2) { sA = 0.5f; sQ = 0.5f; sR = 0.5f; }
    }
    __syncthreads();

    int cur = 0;
    for (int t = 0; t <= TT; ++t) {
        const int ti = t & (TCH - 1);
        if (ti == 0 && t < TT) {
            __syncthreads();
            for (int idx = tid; idx < BPB * TCH; idx += NT) {
                const int b = idx >> 6, i2 = idx & (TCH - 1);
                xsm[b][i2] = x[(bbase + b) * TT + t + i2];
            }
            __syncthreads();
        } else if (ti == 1 && t > TCH) {
            __syncthreads();
            const int tb = t - (TCH + 1);
            for (int idx = tid; idx < BPB * TCH; idx += NT) {
                const int b = idx >> 6, i2 = idx & (TCH - 1);
                out[(bbase + b) * TT + tb + i2] = osm[b][i2];
            }
            __syncthreads();
        }

        if (isL1 && t < TT) {
            // ---- matvec: 9 k-steps, 4 batches, packed gate pairs ----
            u64 a0[4], a1[4];
            a0[0] = bias0; a0[1] = bias0; a0[2] = bias0; a0[3] = bias0;
            a1[0] = bias1; a1[1] = bias1; a1[2] = bias1; a1[3] = bias1;
            const int kb = kq * 9;
            #pragma unroll
            for (int kk = 0; kk < 9; ++kk) {
                const ulonglong2 p01 = *(const ulonglong2*)&hsm[cur][kb + kk][bg * 8];
                const ulonglong2 p23 = *(const ulonglong2*)&hsm[cur][kb + kk][bg * 8 + 4];
                const u64 wA = w1p[kk][0], wB = w1p[kk][1];
                a0[0] = fma2(wA, p01.x, a0[0]); a1[0] = fma2(wB, p01.x, a1[0]);
                a0[1] = fma2(wA, p01.y, a0[1]); a1[1] = fma2(wB, p01.y, a1[1]);
                a0[2] = fma2(wA, p23.x, a0[2]); a1[2] = fma2(wB, p23.x, a1[2]);
                a0[3] = fma2(wA, p23.y, a0[3]); a1[3] = fma2(wB, p23.y, a1[3]);
            }
            // ---- quad reduce-scatter: round 1 over xor 2 ----
            const bool hi2 = (kq & 2) != 0;
            u64 g0 = hi2 ? a0[0] : a0[2];
            u64 g1 = hi2 ? a0[1] : a0[3];
            u64 g2_ = hi2 ? a1[0] : a1[2];
            u64 g3 = hi2 ? a1[1] : a1[3];
            u64 k0 = hi2 ? a0[2] : a0[0];
            u64 k1 = hi2 ? a0[3] : a0[1];
            u64 k2 = hi2 ? a1[2] : a1[0];
            u64 k3 = hi2 ? a1[3] : a1[1];
            k0 = add2(k0, shfl64(g0, 2));
            k1 = add2(k1, shfl64(g1, 2));
            k2 = add2(k2, shfl64(g2_, 2));
            k3 = add2(k3, shfl64(g3, 2));
            // ---- round 2 over xor 1: keep batch kq ----
            const bool hi1 = (kq & 1) != 0;
            u64 s0 = hi1 ? k0 : k1;
            u64 s1 = hi1 ? k2 : k3;
            u64 f0 = hi1 ? k1 : k0;   // {gate_i, gate_f} for batch kq
            u64 f1 = hi1 ? k3 : k2;   // {gate_g, gate_o}
            f0 = add2(f0, shfl64(s0, 1));
            f1 = add2(f1, shfl64(s1, 1));
            // ---- activations for batch bg*4+kq ----
            float gi, gf, gg, go;
            upk2(f0, gi, gf);
            upk2(f1, gg, go);
            const float xb = xsm[bg * 4 + kq][ti];
            gi = fmaf(wx0, xb, gi);
            gf = fmaf(wx1, xb, gf);
            gg = fmaf(wx2, xb, gg);
            go = fmaf(wx3, xb, go);
            const float cc = sigap(gf) * c1 + sigap(gi) * tanhap(gg);
            c1 = cc;
            const float hh = sigap(go) * tanhap(cc);
            *(float2*)&hsm[cur ^ 1][j][bg * 8 + kq * 2] = make_float2(hh, hh);
        } else if (isL2 && t >= 1) {
            // ---- layer 2 for time t-1: reads h1(t-1) = hsm[cur] ----
            float4 p = make_float4(0.f, 0.f, 0.f, 0.f);
            #pragma unroll
            for (int s = 0; s < 9; ++s) {
                const float4 q01 = *(const float4*)&hsm[cur][sg * 9 + s][bgl * 8];
                const float4 q23 = *(const float4*)&hsm[cur][sg * 9 + s][bgl * 8 + 4];
                const float w = w2r[s];
                p.x = fmaf(w, fmaxf(q01.x, 0.f), p.x);
                p.y = fmaf(w, fmaxf(q01.z, 0.f), p.y);
                p.z = fmaf(w, fmaxf(q23.x, 0.f), p.z);
                p.w = fmaf(w, fmaxf(q23.z, 0.f), p.w);
            }
            #pragma unroll
            for (int off = 4; off <= 8; off <<= 1) {
                p.x += __shfl_xor_sync(0xFFFFFFFFu, p.x, off);
                p.y += __shfl_xor_sync(0xFFFFFFFFu, p.y, off);
                p.z += __shfl_xor_sync(0xFFFFFFFFu, p.z, off);
                p.w += __shfl_xor_sync(0xFFFFFFFFu, p.w, off);
            }
            float4 a;
            {
                const float v0 = p.x + fmaf(wh2g, h2[0], b2);
                const float v1 = p.y + fmaf(wh2g, h2[1], b2);
                const float v2 = p.z + fmaf(wh2g, h2[2], b2);
                const float v3 = p.w + fmaf(wh2g, h2[3], b2);
                a.x = fmaf(sQ, tanhap(sA * v0), sR);
                a.y = fmaf(sQ, tanhap(sA * v1), sR);
                a.z = fmaf(sQ, tanhap(sA * v2), sR);
                a.w = fmaf(sQ, tanhap(sA * v3), sR);
            }
            const int lb = bgl * 16;
            float4 Gi, Gf, Gg, Go;
            Gi.x = __shfl_sync(0xFFFFFFFFu, a.x, lb + 0);
            Gi.y = __shfl_sync(0xFFFFFFFFu, a.y, lb + 0);
            Gi.z = __shfl_sync(0xFFFFFFFFu, a.z, lb + 0);
            Gi.w = __shfl_sync(0xFFFFFFFFu, a.w, lb + 0);
            Gf.x = __shfl_sync(0xFFFFFFFFu, a.x, lb + 1);
            Gf.y = __shfl_sync(0xFFFFFFFFu, a.y, lb + 1);
            Gf.z = __shfl_sync(0xFFFFFFFFu, a.z, lb + 1);
            Gf.w = __shfl_sync(0xFFFFFFFFu, a.w, lb + 1);
            Gg.x = __shfl_sync(0xFFFFFFFFu, a.x, lb + 2);
            Gg.y = __shfl_sync(0xFFFFFFFFu, a.y, lb + 2);
            Gg.z = __shfl_sync(0xFFFFFFFFu, a.z, lb + 2);
            Gg.w = __shfl_sync(0xFFFFFFFFu, a.w, lb + 2);
            Go.x = __shfl_sync(0xFFFFFFFFu, a.x, lb + 3);
            Go.y = __shfl_sync(0xFFFFFFFFu, a.y, lb + 3);
            Go.z = __shfl_sync(0xFFFFFFFFu, a.z, lb + 3);
            Go.w = __shfl_sync(0xFFFFFFFFu, a.w, lb + 3);
            c2[0] = Gf.x * c2[0] + Gi.x * Gg.x;
            c2[1] = Gf.y * c2[1] + Gi.y * Gg.y;
            c2[2] = Gf.z * c2[2] + Gi.z * Gg.z;
            c2[3] = Gf.w * c2[3] + Gi.w * Gg.w;
            h2[0] = Go.x * tanhap(c2[0]);
            h2[1] = Go.y * tanhap(c2[1]);
            h2[2] = Go.z * tanhap(c2[2]);
            h2[3] = Go.w * tanhap(c2[3]);
            if (sub == 0) {
                const int slot = (t - 1) & (TCH - 1);
                osm[bgl * 4 + 0][slot] = h2[0];
                osm[bgl * 4 + 1][slot] = h2[1];
                osm[bgl * 4 + 2][slot] = h2[2];
                osm[bgl * 4 + 3][slot] = h2[3];
            }
        }

        __syncthreads();
        cur ^= 1;
    }

    // ---- flush final chunk [TT-TCH, TT) ----
    for (int idx = tid; idx < BPB * TCH; idx += NT) {
        const int b = idx >> 6, i2 = idx & (TCH - 1);
        out[(bbase + b) * TT + (TT - TCH) + i2] = osm[b][i2];
    }
}

extern "C" void kernel_launch(void* const* d_in, const int* in_sizes, int n_in,
                              void* d_out, int out_size) {
    (void)in_sizes; (void)n_in; (void)out_size;
    const float* x    = (const float*)d_in[0];
    const float* Wih1 = (const float*)d_in[1];
    const float* Whh1 = (const float*)d_in[2];
    const float* bih1 = (const float*)d_in[3];
    const float* bhh1 = (const float*)d_in[4];
    const float* Wih2 = (const float*)d_in[5];
    const float* Whh2 = (const float*)d_in[6];
    const float* bih2 = (const float*)d_in[7];
    const float* bhh2 = (const float*)d_in[8];
    float* out = (float*)d_out;

    lstm2_kernel<<<2048 / BPB, NT>>>(x, Wih1, Whh1, bih1, bhh1,
                                     Wih2, Whh2, bih2, bhh2, out);
}